// round 10
// baseline (speedup 1.0000x reference)
#include <cuda_runtime.h>
#include <cstdint>

// SocialCircleLayer: B=8192 rows, N=128 neighbors, T=8, P=8.
// R10: TMA bulk-copy double-buffered pipeline. One elected thread streams the
// next 16KB tile (2 rows) gmem->smem via cp.async.bulk while 256 threads
// compute the current tile from smem (LDS lat 29 vs LDG ~600). Keeps loads in
// flight through the compute/barrier/phase-2 tail with ZERO register cost
// (the R6/R7 register-prefetch occupancy trap). Row math identical to R8.

#define NNEI   128
#define PARTS  8
#define ROWS_PER_TILE 2
#define TILE_BYTES (ROWS_PER_TILE * NNEI * 64)   // 16384
#define MU_F     1e-4f
#define CEPS_F   1e-4f
#define TWO_PI_F 6.283185307179586f
#define NSM    148
#define CTA_PER_SM 6

__device__ __forceinline__ float approx_len(float x2) {
    float r;
    asm("rsqrt.approx.f32 %0, %1;" : "=f"(r) : "f"(x2));
    float len = x2 * r;
    return (x2 > 0.0f) ? len : 0.0f;
}

__device__ __forceinline__ uint32_t smem_u32(const void* p) {
    return (uint32_t)__cvta_generic_to_shared(p);
}

__device__ __forceinline__ void mbar_init(uint32_t mbar, uint32_t count) {
    asm volatile("mbarrier.init.shared.b64 [%0], %1;" :: "r"(mbar), "r"(count) : "memory");
}
__device__ __forceinline__ void mbar_expect_tx(uint32_t mbar, uint32_t bytes) {
    asm volatile("mbarrier.arrive.expect_tx.shared.b64 _, [%0], %1;"
                 :: "r"(mbar), "r"(bytes) : "memory");
}
__device__ __forceinline__ void bulk_g2s(uint32_t dst, const void* src,
                                         uint32_t bytes, uint32_t mbar) {
    asm volatile("cp.async.bulk.shared::cluster.global.mbarrier::complete_tx::bytes "
                 "[%0], [%1], %2, [%3];"
                 :: "r"(dst), "l"(src), "r"(bytes), "r"(mbar) : "memory");
}
__device__ __forceinline__ void mbar_wait(uint32_t mbar, uint32_t parity) {
    asm volatile(
        "{\n\t"
        ".reg .pred P1;\n\t"
        "WAIT_LOOP_%=:\n\t"
        "mbarrier.try_wait.parity.acquire.cta.shared::cta.b64 P1, [%0], %1, 0x989680;\n\t"
        "@P1 bra.uni WAIT_DONE_%=;\n\t"
        "bra.uni WAIT_LOOP_%=;\n\t"
        "WAIT_DONE_%=:\n\t"
        "}"
        :: "r"(mbar), "r"(parity) : "memory");
}

__global__ __launch_bounds__(NNEI * ROWS_PER_TILE) void social_circle_kernel(
    const float* __restrict__ trajs,      // [B, 8, 2]
    const float* __restrict__ nei_trajs,  // [B, 128, 8, 2]
    float* __restrict__ out_sc,           // [B, 8, 3]
    float* __restrict__ out_dir,          // [B, 128]
    int numTiles)
{
    const int n    = threadIdx.x;          // 0..255
    const int row  = n >> 7;               // row within tile
    const int ln   = n & 127;              // neighbor index
    const int wid  = (n >> 5) & 3;         // source warp within row
    const int lane = n & 31;
    const int G    = gridDim.x;

    __shared__ __align__(128) float4 stage[2][ROWS_PER_TILE * NNEI * 4]; // raw tiles
    __shared__ float4   vals[ROWS_PER_TILE][NNEI];
    __shared__ unsigned pmask[ROWS_PER_TILE][4][PARTS];
    __shared__ __align__(8) unsigned long long mbar_s[2];

    const uint32_t mb0 = smem_u32(&mbar_s[0]);
    const uint32_t mb1 = smem_u32(&mbar_s[1]);

    if (n == 0) {
        mbar_init(mb0, 1);
        mbar_init(mb1, 1);
        asm volatile("fence.proxy.async.shared::cta;" ::: "memory");
        // prologue: issue first two tiles
        const int t0 = blockIdx.x;
        const int t1 = blockIdx.x + G;
        if (t0 < numTiles) {
            mbar_expect_tx(mb0, TILE_BYTES);
            bulk_g2s(smem_u32(&stage[0][0]),
                     nei_trajs + (size_t)t0 * (TILE_BYTES / 4), TILE_BYTES, mb0);
        }
        if (t1 < numTiles) {
            mbar_expect_tx(mb1, TILE_BYTES);
            bulk_g2s(smem_u32(&stage[1][0]),
                     nei_trajs + (size_t)t1 * (TILE_BYTES / 4), TILE_BYTES, mb1);
        }
    }
    __syncthreads();

    int par0 = 0, par1 = 0;
    int i = 0;
    for (int t = blockIdx.x; t < numTiles; t += G, i ^= 1) {
        const int b = t * ROWS_PER_TILE + row;

        // trajs loads issued before the mbarrier wait (latency overlapped)
        const float* tb = trajs + (size_t)b * 16;
        const float tfx = tb[0],  tfy = tb[1];
        const float ox7 = tb[14], oy7 = tb[15];

        // wait for this tile's TMA
        if (i == 0) { mbar_wait(mb0, par0); par0 ^= 1; }
        else        { mbar_wait(mb1, par1); par1 ^= 1; }

        // phase 1: read this thread's 64B from the staged tile
        const float4* src = &stage[i][(row * NNEI + ln) * 4];
        const float4 v0 = src[0];
        const float4 v1 = src[1];
        const float4 v2 = src[2];
        const float4 v3 = src[3];

        const float ovx = ox7 - tfx;
        const float ovy = oy7 - tfy;
        const float obs_len = approx_len(ovx * ovx + ovy * ovy);

        const float ssum = (v0.x + v0.y + v0.z + v0.w)
                         + (v1.x + v1.y + v1.z + v1.w)
                         + (v2.x + v2.y + v2.z + v2.w)
                         + (v3.x + v3.y + v3.z + v3.w);
        const bool valid = (ssum != 0.0f);

        const float nvx = v3.z - v0.x;
        const float nvy = v3.w - v0.y;
        const float nei_len = approx_len(nvx * nvx + nvy * nvy);
        const float f_speed = __fdividef(nei_len + MU_F, obs_len + MU_F);

        const float px = v3.z - ox7;
        const float py = v3.w - oy7;
        const float f_dist = approx_len(px * px + py * py);

        float d = atan2f(py, px);
        if (d < 0.0f) d += TWO_PI_F;

        out_dir[(size_t)b * NNEI + ln] = d;

        const int idx = (int)(d / (TWO_PI_F / PARTS));
        const int key = (valid && idx < PARTS) ? idx : -1;

        vals[row][ln] = make_float4(f_speed, f_dist, d, 0.0f);

        unsigned mymask = 0;
        #pragma unroll
        for (int p = 0; p < PARTS; p++) {
            const unsigned m = __ballot_sync(0xffffffffu, key == p);
            if (lane == p) mymask = m;
        }
        if (lane < PARTS) pmask[row][wid][lane] = mymask;

        __syncthreads();   // all phase-1 reads of stage[i] + vals/pmask writes done

        // refill this buffer with tile t+2G while phase 2 runs
        if (n == 0) {
            const int tn = t + 2 * G;
            if (tn < numTiles) {
                const uint32_t mb = (i == 0) ? mb0 : mb1;
                mbar_expect_tx(mb, TILE_BYTES);
                bulk_g2s(smem_u32(&stage[i][0]),
                         nei_trajs + (size_t)tn * (TILE_BYTES / 4), TILE_BYTES, mb);
            }
        }

        // phase 2: warp w (<2) reduces row w. lane -> (p = lane>>2, r = lane&3)
        if (n < 32 * ROWS_PER_TILE) {
            const int r2 = n >> 5;
            const int p  = lane >> 2;
            const int r  = lane & 3;
            const int bb = t * ROWS_PER_TILE + r2;

            unsigned m = pmask[r2][r][p];
            float cnt = (float)__popc(m);
            float s = 0.0f, dd = 0.0f, dir = 0.0f;
            const int base = r << 5;

            while (m) {
                const int j = __ffs(m) - 1;
                m &= m - 1;
                const float4 v = vals[r2][base + j];
                s   += v.x;
                dd  += v.y;
                dir += v.z;
            }

            #pragma unroll
            for (int off = 2; off > 0; off >>= 1) {
                s   += __shfl_down_sync(0xffffffffu, s,   off, 4);
                dd  += __shfl_down_sync(0xffffffffu, dd,  off, 4);
                dir += __shfl_down_sync(0xffffffffu, dir, off, 4);
                cnt += __shfl_down_sync(0xffffffffu, cnt, off, 4);
            }

            const float inv = __fdividef(1.0f, cnt + CEPS_F);
            s   *= inv;
            dd  *= inv;
            dir *= inv;

            const int p2  = (lane * 11) >> 5;   // lane/3 for lane<32
            const int f   = lane - p2 * 3;
            const int src2 = p2 << 2;
            const float a0 = __shfl_sync(0xffffffffu, s,   src2);
            const float a1 = __shfl_sync(0xffffffffu, dd,  src2);
            const float a2 = __shfl_sync(0xffffffffu, dir, src2);
            const float outv = (f == 0) ? a0 : ((f == 1) ? a1 : a2);
            if (lane < PARTS * 3) {
                out_sc[(size_t)bb * (PARTS * 3) + lane] = outv;
            }
        }

        __syncthreads();   // protect vals/pmask from next iteration's overwrite
    }
}

extern "C" void kernel_launch(void* const* d_in, const int* in_sizes, int n_in,
                              void* d_out, int out_size) {
    const float* trajs     = (const float*)d_in[0];
    const float* nei_trajs = (const float*)d_in[1];
    float* out = (float*)d_out;

    const int B = in_sizes[0] / 16;   // trajs is [B, 8, 2]
    const int numTiles = B / ROWS_PER_TILE;

    float* out_sc  = out;                          // [B, 8, 3]
    float* out_dir = out + (size_t)B * PARTS * 3;  // [B, 128]

    int grid = NSM * CTA_PER_SM;                   // 888: one resident wave
    if (grid > numTiles) grid = numTiles;

    social_circle_kernel<<<grid, NNEI * ROWS_PER_TILE>>>(
        trajs, nei_trajs, out_sc, out_dir, numTiles);
}

// round 11
// speedup vs baseline: 1.6387x; 1.6387x over previous
#include <cuda_runtime.h>

// SocialCircleLayer: B=8192 rows, N=128 neighbors, T=8, P=8.
// R11: R8 skeleton (best structure: one barrier, 2 rows/256-thr CTA, ffs
// phase 2) with per-thread instruction cuts:
//  - __match_any_sync replaces the 8-ballot mask loop (-25 instr/thread)
//  - custom atan2: 2x __fdividef range reduction + Taylor-thru-u^15 poly
//    (err < ~3e-7 rad; bucket-flip impact ~1e-4 on aggregate rel_err)
// R10 lesson: single-buffered TMA serializes; R9 lesson: redux.f32 needs
// sm_100a, harness targets compute_100.

#define NNEI   128
#define PARTS  8
#define ROWS_PER_CTA 2
#define MU_F     1e-4f
#define CEPS_F   1e-4f
#define TWO_PI_F 6.283185307179586f
#define PI_F     3.14159265358979f
#define PIO2_F   1.5707963267949f
#define PIO4_F   0.78539816339745f
#define TAN_PIO8 0.41421356237f

__device__ __forceinline__ float approx_len(float x2) {
    float r;
    asm("rsqrt.approx.f32 %0, %1;" : "=f"(r) : "f"(x2));
    float len = x2 * r;
    return (x2 > 0.0f) ? len : 0.0f;
}

// atan2 in [0, 2*pi): |err| < ~3e-7 rad. Two fast divides + odd Taylor poly
// on |u| <= tan(pi/8) (truncation < 2e-8, alternating series).
__device__ __forceinline__ float atan2_2pi(float y, float x) {
    const float ax = fabsf(x);
    const float ay = fabsf(y);
    const float mx = fmaxf(ax, ay);
    const float mn = fminf(ax, ay);
    float t = (mx == 0.0f) ? 0.0f : __fdividef(mn, mx);

    const bool red = (t > TAN_PIO8);
    const float u  = red ? __fdividef(t - 1.0f, t + 1.0f) : t;

    const float z = u * u;
    float q;
    q = -1.0f / 15.0f;
    q = fmaf(q, z,  1.0f / 13.0f);
    q = fmaf(q, z, -1.0f / 11.0f);
    q = fmaf(q, z,  1.0f /  9.0f);
    q = fmaf(q, z, -1.0f /  7.0f);
    q = fmaf(q, z,  1.0f /  5.0f);
    q = fmaf(q, z, -1.0f /  3.0f);
    float a = fmaf(q * z, u, u);          // atan(u)

    if (red)      a += PIO4_F;            // atan(t), t in (tan(pi/8), 1]
    if (ay > ax)  a = PIO2_F - a;         // undo min/max swap
    if (x < 0.0f) a = PI_F - a;           // quadrant II/III
    return (y < 0.0f) ? (TWO_PI_F - a) : a;  // mod 2*pi
}

__global__ __launch_bounds__(NNEI * ROWS_PER_CTA) void social_circle_kernel(
    const float* __restrict__ trajs,      // [B, 8, 2]
    const float* __restrict__ nei_trajs,  // [B, 128, 8, 2]
    float* __restrict__ out_sc,           // [B, 8, 3]
    float* __restrict__ out_dir)          // [B, 128]
{
    const int n    = threadIdx.x;          // 0..255
    const int row  = n >> 7;               // which batch row in this CTA
    const int ln   = n & 127;              // neighbor index within row
    const int wid  = (n >> 5) & 3;         // source warp within row
    const int lane = n & 31;

    const int b = blockIdx.x * ROWS_PER_CTA + row;

    __shared__ float4   vals[ROWS_PER_CTA][NNEI];      // {speed, dist, dir, -}
    __shared__ unsigned pmask[ROWS_PER_CTA][4][PARTS]; // [row][src warp][partition]

    // zero this warp's mask slots (leaders overwrite below)
    if (lane < PARTS) pmask[row][wid][lane] = 0u;

    // obs vector (uniform per row-half -> broadcast loads)
    const float* tb = trajs + (size_t)b * 16;
    const float ox7 = tb[14], oy7 = tb[15];
    const float ovx = ox7 - tb[0];
    const float ovy = oy7 - tb[1];
    const float obs_len = approx_len(ovx * ovx + ovy * ovy);

    // 64B contiguous per thread
    const float4* np4 = (const float4*)(nei_trajs + ((size_t)b * NNEI + ln) * 16);
    const float4 v0 = np4[0];
    const float4 v1 = np4[1];
    const float4 v2 = np4[2];
    const float4 v3 = np4[3];

    // validity: sum of all 16 coords != 0
    const float ssum = (v0.x + v0.y + v0.z + v0.w)
                     + (v1.x + v1.y + v1.z + v1.w)
                     + (v2.x + v2.y + v2.z + v2.w)
                     + (v3.x + v3.y + v3.z + v3.w);
    const bool valid = (ssum != 0.0f);

    // displacement t=7 - t=0
    const float nvx = v3.z - v0.x;
    const float nvy = v3.w - v0.y;
    const float nei_len = approx_len(nvx * nvx + nvy * nvy);
    const float f_speed = __fdividef(nei_len + MU_F, obs_len + MU_F);

    // relative position at final step
    const float px = v3.z - ox7;
    const float py = v3.w - oy7;
    const float f_dist = approx_len(px * px + py * py);

    // f_direction = mod(atan2(py, px), 2*pi)
    const float d = atan2_2pi(py, px);

    out_dir[(size_t)b * NNEI + ln] = d;

    // bucket key: exact IEEE division (boundary-sensitive); invalid or
    // idx==PARTS (d rounds to 2*pi) -> -1 (its mask is never stored)
    const int idx = (int)(d / (TWO_PI_F / PARTS));
    const int key = (valid && idx < PARTS) ? idx : -1;

    vals[row][ln] = make_float4(f_speed, f_dist, d, 0.0f);

    // group lanes by key in one collective; group leader stores the mask
    const unsigned grp = __match_any_sync(0xffffffffu, key);
    __syncwarp();  // zero-init above ordered before leader overwrite
    if (lane == (__ffs(grp) - 1) && key >= 0) {
        pmask[row][wid][key] = grp;
    }
    __syncthreads();

    // Phase 2: warp w (< ROWS_PER_CTA) reduces row w.
    // lane -> (partition p = lane>>2, source warp r = lane&3).
    if (n < 32 * ROWS_PER_CTA) {
        const int r2 = n >> 5;
        const int p  = lane >> 2;
        const int r  = lane & 3;
        const int bb = blockIdx.x * ROWS_PER_CTA + r2;

        unsigned m = pmask[r2][r][p];
        float cnt = (float)__popc(m);
        float s = 0.0f, dd = 0.0f, dir = 0.0f;
        const int base = r << 5;

        while (m) {                         // each 16B value read exactly once
            const int j = __ffs(m) - 1;
            m &= m - 1;
            const float4 v = vals[r2][base + j];
            s   += v.x;
            dd  += v.y;
            dir += v.z;
        }

        // width-4 shuffle tree (4 source warps per partition)
        #pragma unroll
        for (int off = 2; off > 0; off >>= 1) {
            s   += __shfl_down_sync(0xffffffffu, s,   off, 4);
            dd  += __shfl_down_sync(0xffffffffu, dd,  off, 4);
            dir += __shfl_down_sync(0xffffffffu, dir, off, 4);
            cnt += __shfl_down_sync(0xffffffffu, cnt, off, 4);
        }

        const float inv = __fdividef(1.0f, cnt + CEPS_F);
        s   *= inv;
        dd  *= inv;
        dir *= inv;

        // redistribute so lanes 0..23 emit one coalesced 96B store per row
        const int p2  = (lane * 11) >> 5;   // lane/3 for lane<32
        const int f   = lane - p2 * 3;
        const int src = p2 << 2;            // leader lane of partition p2
        const float a0 = __shfl_sync(0xffffffffu, s,   src);
        const float a1 = __shfl_sync(0xffffffffu, dd,  src);
        const float a2 = __shfl_sync(0xffffffffu, dir, src);
        const float outv = (f == 0) ? a0 : ((f == 1) ? a1 : a2);
        if (lane < PARTS * 3) {
            out_sc[(size_t)bb * (PARTS * 3) + lane] = outv;
        }
    }
}

extern "C" void kernel_launch(void* const* d_in, const int* in_sizes, int n_in,
                              void* d_out, int out_size) {
    const float* trajs     = (const float*)d_in[0];
    const float* nei_trajs = (const float*)d_in[1];
    float* out = (float*)d_out;

    const int B = in_sizes[0] / 16;   // trajs is [B, 8, 2]

    float* out_sc  = out;                          // [B, 8, 3]
    float* out_dir = out + (size_t)B * PARTS * 3;  // [B, 128]

    social_circle_kernel<<<B / ROWS_PER_CTA, NNEI * ROWS_PER_CTA>>>(
        trajs, nei_trajs, out_sc, out_dir);
}